// round 1
// baseline (speedup 1.0000x reference)
#include <cuda_runtime.h>
#include <cuda_bf16.h>
#include <math.h>
#include <stdint.h>

#define BATCH     1024
#define NF        256
#define NS        100000
#define INV_TEMP  20.0f
#define NTILE     128
#define NBLK      ((NS + NTILE - 1) / NTILE)   /* 782 */
#define MCHUNK    128
#define LDSS      264                           /* 256 + 8 bf16 pad: conflict-free ldmatrix */
#define SMEM_BYTES ((MCHUNK*LDSS + NTILE*LDSS) * 2 + 2 * 2 * 128 * 4)

__device__ __nv_bfloat16 g_a_bf16[BATCH * NF];
__device__ float g_pm[(size_t)NBLK * BATCH];
__device__ float g_ps[(size_t)NBLK * BATCH];
__device__ float g_tlogit[BATCH];
__device__ float g_rownll[BATCH];
__device__ int   g_tstride;

// ---------------------------------------------------------------- helpers
__device__ __forceinline__ uint32_t sptr(const void* p) {
    return (uint32_t)__cvta_generic_to_shared(p);
}

__device__ __forceinline__ void ldsm4(uint32_t addr, uint32_t& r0, uint32_t& r1,
                                      uint32_t& r2, uint32_t& r3) {
    asm volatile("ldmatrix.sync.aligned.m8n8.x4.shared.b16 {%0,%1,%2,%3}, [%4];"
                 : "=r"(r0), "=r"(r1), "=r"(r2), "=r"(r3) : "r"(addr));
}

__device__ __forceinline__ void mma16816(float c[4], const uint32_t a[4],
                                         uint32_t b0, uint32_t b1) {
    asm volatile(
        "mma.sync.aligned.m16n8k16.row.col.f32.bf16.bf16.f32 "
        "{%0,%1,%2,%3},{%4,%5,%6,%7},{%8,%9},{%0,%1,%2,%3};"
        : "+f"(c[0]), "+f"(c[1]), "+f"(c[2]), "+f"(c[3])
        : "r"(a[0]), "r"(a[1]), "r"(a[2]), "r"(a[3]), "r"(b0), "r"(b1));
}

// ---------------------------------------------------------------- prep kernels
__global__ void prep_kernel(const float* __restrict__ a) {
    int i = blockIdx.x * blockDim.x + threadIdx.x;
    if (i < BATCH * NF) g_a_bf16[i] = __float2bfloat16(a[i]);
}

// targets may be int64 or int32 depending on jax x64; detect safely within
// the first 2KB (valid for both layouts). Values are < 1e5, so int64 hi=0.
__global__ void detect_kernel(const int* __restrict__ t32) {
    if (threadIdx.x == 0 && blockIdx.x == 0) {
        int s = 2;
        for (int i = 1; i < 512; i += 2)
            if (t32[i] != 0) { s = 1; break; }
        g_tstride = s;
    }
}

// exact fp32 target logit per row
__global__ void tlogit_kernel(const float* __restrict__ a,
                              const int* __restrict__ t32,
                              const float* __restrict__ f) {
    int row = blockIdx.x;
    int tid = threadIdx.x;  // 256 threads
    long long tgt = (long long)t32[row * g_tstride];
    float p = a[row * NF + tid] * f[tgt * NF + tid];
    for (int off = 16; off; off >>= 1) p += __shfl_xor_sync(~0u, p, off);
    __shared__ float sm[8];
    if ((tid & 31) == 0) sm[tid >> 5] = p;
    __syncthreads();
    if (tid == 0) {
        float s = 0.f;
        #pragma unroll
        for (int w = 0; w < 8; w++) s += sm[w];
        g_tlogit[row] = s * INV_TEMP;
    }
}

// ---------------------------------------------------------------- fused GEMM + online softmax partials
extern __shared__ char smem_raw[];

__global__ void __launch_bounds__(256, 1) gemm_lse_kernel(const float* __restrict__ feats) {
    __nv_bfloat16* As = (__nv_bfloat16*)smem_raw;            // [128][264]
    __nv_bfloat16* Bs = As + MCHUNK * LDSS;                  // [128][264]
    float* red_m = (float*)(Bs + NTILE * LDSS);              // [2][128]
    float* red_s = red_m + 2 * 128;                          // [2][128]

    const int tid  = threadIdx.x;
    const int lane = tid & 31, warp = tid >> 5;
    const int wm = warp >> 1, wn = warp & 1;
    const int nbase = blockIdx.x * NTILE;

    // Load feature slab once (fp32 -> bf16)
    for (int i = tid; i < NTILE * (NF / 4); i += 256) {
        int r  = i >> 6;        // 64 float4 per row
        int c4 = i & 63;
        int srow = nbase + r;
        float4 v = make_float4(0.f, 0.f, 0.f, 0.f);
        if (srow < NS) v = ((const float4*)feats)[(size_t)srow * (NF / 4) + c4];
        __nv_bfloat162 p0 = __floats2bfloat162_rn(v.x, v.y);
        __nv_bfloat162 p1 = __floats2bfloat162_rn(v.z, v.w);
        uint2 u;
        u.x = *(uint32_t*)&p0;
        u.y = *(uint32_t*)&p1;
        *(uint2*)(Bs + r * LDSS + c4 * 4) = u;
    }

    const int aRow = lane & 15,                       aKo = (lane >> 4) << 3;
    const int bRow = (lane & 7) + ((lane >> 4) << 3), bKo = ((lane >> 3) & 1) << 3;
    const int qr = lane >> 2, qc = lane & 3;

    #pragma unroll 1
    for (int mc = 0; mc < BATCH / MCHUNK; mc++) {
        __syncthreads();
        // A chunk (bf16, L2-resident) -> SMEM
        for (int i = tid; i < MCHUNK * (NF / 8); i += 256) {
            int r  = i >> 5;    // 32 uint4 per row
            int c8 = i & 31;
            uint4 v = ((const uint4*)g_a_bf16)[(size_t)(mc * MCHUNK + r) * (NF / 8) + c8];
            *(uint4*)(As + r * LDSS + c8 * 8) = v;
        }
        __syncthreads();

        float acc[2][8][4];
        #pragma unroll
        for (int mf = 0; mf < 2; mf++)
            #pragma unroll
            for (int nf = 0; nf < 8; nf++)
                #pragma unroll
                for (int j = 0; j < 4; j++) acc[mf][nf][j] = 0.f;

        #pragma unroll 2
        for (int kk = 0; kk < NF; kk += 16) {
            uint32_t afrag[2][4];
            #pragma unroll
            for (int mf = 0; mf < 2; mf++) {
                uint32_t addr = sptr(As + (wm * 32 + mf * 16 + aRow) * LDSS + kk + aKo);
                ldsm4(addr, afrag[mf][0], afrag[mf][1], afrag[mf][2], afrag[mf][3]);
            }
            uint32_t bfrag[8][2];
            #pragma unroll
            for (int np = 0; np < 4; np++) {
                uint32_t addr = sptr(Bs + (wn * 64 + np * 16 + bRow) * LDSS + kk + bKo);
                uint32_t r0, r1, r2, r3;
                ldsm4(addr, r0, r1, r2, r3);
                bfrag[np * 2][0] = r0;  bfrag[np * 2][1] = r1;
                bfrag[np * 2 + 1][0] = r2;  bfrag[np * 2 + 1][1] = r3;
            }
            #pragma unroll
            for (int mf = 0; mf < 2; mf++)
                #pragma unroll
                for (int nf = 0; nf < 8; nf++)
                    mma16816(acc[mf][nf], afrag[mf], bfrag[nf][0], bfrag[nf][1]);
        }

        // per-row online-softmax partials over this 128x128 tile
        #pragma unroll
        for (int mf = 0; mf < 2; mf++) {
            #pragma unroll
            for (int hi = 0; hi < 2; hi++) {
                float m = -INFINITY;
                #pragma unroll
                for (int nf = 0; nf < 8; nf++)
                    #pragma unroll
                    for (int j = 0; j < 2; j++) {
                        int cg = nbase + wn * 64 + nf * 8 + qc * 2 + j;
                        float v = acc[mf][nf][hi * 2 + j] * INV_TEMP;
                        if (cg < NS) m = fmaxf(m, v);
                    }
                m = fmaxf(m, __shfl_xor_sync(~0u, m, 1));
                m = fmaxf(m, __shfl_xor_sync(~0u, m, 2));
                float s = 0.f;
                #pragma unroll
                for (int nf = 0; nf < 8; nf++)
                    #pragma unroll
                    for (int j = 0; j < 2; j++) {
                        int cg = nbase + wn * 64 + nf * 8 + qc * 2 + j;
                        float v = acc[mf][nf][hi * 2 + j] * INV_TEMP;
                        if (cg < NS) s += __expf(v - m);
                    }
                s += __shfl_xor_sync(~0u, s, 1);
                s += __shfl_xor_sync(~0u, s, 2);
                if (qc == 0) {
                    int rl = wm * 32 + mf * 16 + hi * 8 + qr;
                    red_m[wn * 128 + rl] = m;
                    red_s[wn * 128 + rl] = s;
                }
            }
        }
        __syncthreads();
        if (tid < 128) {
            float m0 = red_m[tid], m1 = red_m[128 + tid];
            float s0 = red_s[tid], s1 = red_s[128 + tid];
            float M = fmaxf(m0, m1);                       // m0 always finite (cols 0-31 valid)
            float S = s0 * __expf(m0 - M) + s1 * __expf(m1 - M);
            int grow = mc * MCHUNK + tid;
            g_pm[(size_t)blockIdx.x * BATCH + grow] = M;
            g_ps[(size_t)blockIdx.x * BATCH + grow] = S;
        }
    }
}

// ---------------------------------------------------------------- cross-block LSE merge
__global__ void lse_kernel() {
    int row = blockIdx.x;
    int tid = threadIdx.x;  // 256 threads
    float M = -INFINITY, S = 0.f;
    for (int b = tid; b < NBLK; b += 256) {
        float m = g_pm[(size_t)b * BATCH + row];
        float s = g_ps[(size_t)b * BATCH + row];
        float nM = fmaxf(M, m);
        S = S * __expf(M - nM) + s * __expf(m - nM);
        M = nM;
    }
    for (int off = 16; off; off >>= 1) {
        float m = __shfl_xor_sync(~0u, M, off);
        float s = __shfl_xor_sync(~0u, S, off);
        float nM = fmaxf(M, m);
        S = S * __expf(M - nM) + s * __expf(m - nM);
        M = nM;
    }
    __shared__ float sm[8], ss[8];
    int w = tid >> 5, ln = tid & 31;
    if (ln == 0) { sm[w] = M; ss[w] = S; }
    __syncthreads();
    if (tid == 0) {
        float Mv = sm[0], Sv = ss[0];
        #pragma unroll
        for (int i = 1; i < 8; i++) {
            float m = sm[i], s = ss[i];
            float nM = fmaxf(Mv, m);
            Sv = Sv * __expf(Mv - nM) + s * __expf(m - nM);
            Mv = nM;
        }
        g_rownll[row] = Mv + logf(Sv) - g_tlogit[row];
    }
}

__global__ void mean_kernel(float* __restrict__ out) {
    __shared__ float sm[32];
    int tid = threadIdx.x;  // 1024 threads
    float v = g_rownll[tid];
    for (int off = 16; off; off >>= 1) v += __shfl_xor_sync(~0u, v, off);
    if ((tid & 31) == 0) sm[tid >> 5] = v;
    __syncthreads();
    if (tid < 32) {
        float x = sm[tid];
        for (int off = 16; off; off >>= 1) x += __shfl_xor_sync(~0u, x, off);
        if (tid == 0) out[0] = x / (float)BATCH;
    }
}

// ---------------------------------------------------------------- launch
extern "C" void kernel_launch(void* const* d_in, const int* in_sizes, int n_in,
                              void* d_out, int out_size) {
    const float* a   = (const float*)d_in[0];   // inputs   [1024,256] f32
    const int*   t32 = (const int*)d_in[1];     // targets  [1024] i64 or i32
    const float* f   = (const float*)d_in[2];   // features [100000,256] f32
    float* out = (float*)d_out;

    cudaFuncSetAttribute(gemm_lse_kernel,
                         cudaFuncAttributeMaxDynamicSharedMemorySize, SMEM_BYTES);

    prep_kernel<<<(BATCH * NF + 255) / 256, 256>>>(a);
    detect_kernel<<<1, 32>>>(t32);
    tlogit_kernel<<<BATCH, 256>>>(a, t32, f);
    gemm_lse_kernel<<<NBLK, 256, SMEM_BYTES>>>(f);
    lse_kernel<<<BATCH, 256>>>();
    mean_kernel<<<1, 1024>>>(out);
}